// round 1
// baseline (speedup 1.0000x reference)
#include <cuda_runtime.h>
#include <cuda_bf16.h>

// Problem: out[b,s,n,c] = x[b,s,n,c] + pe[n,c]
//   x: (8, 16, 1024, 256) fp32  -> 32M elements
//   pe[n, c] : c even -> sin(n / (2000*(c/2)/256 + 0.01))
//              c odd  -> cos(n / (2000*((c-1)/2)/256 + 0.01))
//
// Strategy: build 1MB pe table in __device__ global scratch (accurate
// sinf/cosf, range-reduced), then stream x + pe with float4 vectors.
// pe (1MB) lives in L2 across the whole streaming pass.

#define N_POS 1024
#define D_DIM 256
#define PE_ELEMS (N_POS * D_DIM)      // 262144 floats
#define PE_VEC   (PE_ELEMS / 4)       // 65536 float4 -> mask 0xFFFF

__device__ float4 g_pe[PE_VEC];       // 1 MB scratch (allowed: __device__ global)

__global__ void pe_init_kernel() {
    int i = blockIdx.x * blockDim.x + threadIdx.x;   // float4 index, 0..65535
    if (i >= PE_VEC) return;
    int base = i * 4;                  // element index of first lane
    int n = base >> 8;                 // base / 256
    int c0 = base & 255;               // base % 256 (always multiple of 4)
    float fn = (float)n;
    float4 v;
    float* vp = &v.x;
#pragma unroll
    for (int j = 0; j < 4; ++j) {
        int c = c0 + j;
        int k = c >> 1;
        float denom = (2000.0f / 256.0f) * (float)k + 0.01f;
        float angle = fn / denom;
        vp[j] = (c & 1) ? cosf(angle) : sinf(angle);
    }
    g_pe[i] = v;
}

__global__ void __launch_bounds__(256) add_pe_kernel(const float4* __restrict__ x,
                                                     float4* __restrict__ out,
                                                     int total_vec) {
    int v = blockIdx.x * blockDim.x + threadIdx.x;
    if (v >= total_vec) return;
    float4 a = x[v];
    float4 p = g_pe[v & (PE_VEC - 1)];
    a.x += p.x; a.y += p.y; a.z += p.z; a.w += p.w;
    out[v] = a;
}

extern "C" void kernel_launch(void* const* d_in, const int* in_sizes, int n_in,
                              void* d_out, int out_size) {
    const float4* x = (const float4*)d_in[0];
    float4* out = (float4*)d_out;
    int total = in_sizes[0];          // 8*16*1024*256 = 33554432
    int total_vec = total / 4;        // 8388608

    pe_init_kernel<<<PE_VEC / 256, 256>>>();
    add_pe_kernel<<<(total_vec + 255) / 256, 256>>>(x, out, total_vec);
}